// round 1
// baseline (speedup 1.0000x reference)
#include <cuda_runtime.h>
#include <math.h>

#define NN 50000
#define EE 800000
#define ET (EE + NN)

// ---------------- scratch (device globals; allocation-free rule) ----------
__device__ float    g_h1[NN * 128];     // layer1 projection
__device__ float    g_as1[NN * 4];
__device__ float    g_ad1[NN * 4];
__device__ unsigned g_m1[NN * 4];       // encoded segment max
__device__ float    g_den1[NN * 4];
__device__ float    g_e1[ET * 4];       // per-edge logits -> exp values
__device__ float    g_agg1[NN * 128];   // layer1 aggregate -> activated input of layer2
__device__ float    g_h2[NN * 128];     // layer2 projection
__device__ float    g_as2[NN];
__device__ float    g_ad2[NN];
__device__ unsigned g_m2[NN];
__device__ float    g_den2[NN];
__device__ float    g_e2[ET];

// order-preserving float<->uint encoding for atomicMax
__device__ __forceinline__ unsigned fenc(float f) {
    unsigned u = __float_as_uint(f);
    return (u & 0x80000000u) ? ~u : (u | 0x80000000u);
}
__device__ __forceinline__ float fdec(unsigned u) {
    return (u & 0x80000000u) ? __uint_as_float(u & 0x7FFFFFFFu)
                             : __uint_as_float(~u);
}
__device__ __forceinline__ float lrelu(float x) { return x > 0.f ? x : 0.2f * x; }
__device__ __forceinline__ float elu(float x)   { return x > 0.f ? x : expm1f(x); }

// ---------------- init: zero accumulators / maxima ------------------------
__global__ void k_init() {
    int i = blockIdx.x * blockDim.x + threadIdx.x;
    int stride = gridDim.x * blockDim.x;
    for (int j = i; j < NN * 128; j += stride) g_agg1[j] = 0.f;
    for (int j = i; j < NN * 4;   j += stride) { g_den1[j] = 0.f; g_m1[j] = 0u; }
    for (int j = i; j < NN;       j += stride) { g_den2[j] = 0.f; g_m2[j] = 0u; }
    // g_agg2 is d_out-side accumulate? no: keep separate agg2
}
__device__ float g_agg2[NN * 128];
__global__ void k_init2() {
    int i = blockIdx.x * blockDim.x + threadIdx.x;
    int stride = gridDim.x * blockDim.x;
    for (int j = i; j < NN * 128; j += stride) g_agg2[j] = 0.f;
}

// ---------------- GEMM: [NN,128] @ [128,128] ------------------------------
// layer==0: X=Xext -> g_h1 ; layer==1: X=g_agg1 -> g_h2
__global__ void k_gemm(const float* __restrict__ Xext,
                       const float* __restrict__ W, int layer) {
    const float* __restrict__ X = (layer == 0) ? Xext : g_agg1;
    float* __restrict__ H = (layer == 0) ? g_h1 : g_h2;

    __shared__ float xs[64][128];
    int row0 = blockIdx.x * 64;

    for (int i = threadIdx.x; i < 64 * 32; i += 256) {
        int r = i >> 5, c4 = i & 31;
        int row = row0 + r;
        float4 v = make_float4(0.f, 0.f, 0.f, 0.f);
        if (row < NN) v = ((const float4*)X)[row * 32 + c4];
        *(float4*)(&xs[r][c4 * 4]) = v;
    }
    __syncthreads();

    int tc = threadIdx.x & 31;   // col group (4 cols)
    int tr = threadIdx.x >> 5;   // row group (8 rows)
    float acc[8][4];
#pragma unroll
    for (int r = 0; r < 8; r++)
#pragma unroll
        for (int j = 0; j < 4; j++) acc[r][j] = 0.f;

#pragma unroll 8
    for (int k = 0; k < 128; k++) {
        float4 w = ((const float4*)W)[k * 32 + tc];
#pragma unroll
        for (int r = 0; r < 8; r++) {
            float xv = xs[tr * 8 + r][k];
            acc[r][0] += xv * w.x;
            acc[r][1] += xv * w.y;
            acc[r][2] += xv * w.z;
            acc[r][3] += xv * w.w;
        }
    }
#pragma unroll
    for (int r = 0; r < 8; r++) {
        int row = row0 + tr * 8 + r;
        if (row < NN)
            ((float4*)H)[row * 32 + tc] =
                make_float4(acc[r][0], acc[r][1], acc[r][2], acc[r][3]);
    }
}

// ---------------- per-node attention halves --------------------------------
// layer1: heads=4, 32 channels each (warp-level reduce per head)
__global__ void k_alpha1(const float* __restrict__ asrc,
                         const float* __restrict__ adst) {
    int n = blockIdx.x;
    int t = threadIdx.x;           // channel 0..127
    float h = g_h1[n * 128 + t];
    float vs = h * asrc[t];
    float vd = h * adst[t];
#pragma unroll
    for (int off = 16; off; off >>= 1) {
        vs += __shfl_down_sync(0xffffffffu, vs, off);
        vd += __shfl_down_sync(0xffffffffu, vd, off);
    }
    if ((t & 31) == 0) {
        g_as1[n * 4 + (t >> 5)] = vs;
        g_ad1[n * 4 + (t >> 5)] = vd;
    }
}

// layer2: heads=1, 128 channels (block reduce)
__global__ void k_alpha2(const float* __restrict__ asrc,
                         const float* __restrict__ adst) {
    __shared__ float ss[4], sd[4];
    int n = blockIdx.x;
    int t = threadIdx.x;
    float h = g_h2[n * 128 + t];
    float vs = h * asrc[t];
    float vd = h * adst[t];
#pragma unroll
    for (int off = 16; off; off >>= 1) {
        vs += __shfl_down_sync(0xffffffffu, vs, off);
        vd += __shfl_down_sync(0xffffffffu, vd, off);
    }
    if ((t & 31) == 0) { ss[t >> 5] = vs; sd[t >> 5] = vd; }
    __syncthreads();
    if (t == 0) {
        g_as2[n] = ss[0] + ss[1] + ss[2] + ss[3];
        g_ad2[n] = sd[0] + sd[1] + sd[2] + sd[3];
    }
}

// ---------------- layer1 edge kernels --------------------------------------
__global__ void k_edgeA1(const int* __restrict__ ei) {
    int e = blockIdx.x * blockDim.x + threadIdx.x;
    if (e >= ET) return;
    int s, d;
    if (e < EE) { s = ei[e]; d = ei[EE + e]; } else { s = e - EE; d = s; }
    float4 a = ((const float4*)g_as1)[s];
    float4 b = ((const float4*)g_ad1)[d];
    float4 l;
    l.x = lrelu(a.x + b.x); l.y = lrelu(a.y + b.y);
    l.z = lrelu(a.z + b.z); l.w = lrelu(a.w + b.w);
    ((float4*)g_e1)[e] = l;
    atomicMax(&g_m1[d * 4 + 0], fenc(l.x));
    atomicMax(&g_m1[d * 4 + 1], fenc(l.y));
    atomicMax(&g_m1[d * 4 + 2], fenc(l.z));
    atomicMax(&g_m1[d * 4 + 3], fenc(l.w));
}

__global__ void k_edgeB1(const int* __restrict__ ei) {
    int e = blockIdx.x * blockDim.x + threadIdx.x;
    if (e >= ET) return;
    int d = (e < EE) ? ei[EE + e] : (e - EE);
    float4 l = ((const float4*)g_e1)[e];
    uint4 mu = ((const uint4*)g_m1)[d];
    float4 ex;
    ex.x = __expf(l.x - fdec(mu.x));
    ex.y = __expf(l.y - fdec(mu.y));
    ex.z = __expf(l.z - fdec(mu.z));
    ex.w = __expf(l.w - fdec(mu.w));
    ((float4*)g_e1)[e] = ex;
    atomicAdd(&g_den1[d * 4 + 0], ex.x);
    atomicAdd(&g_den1[d * 4 + 1], ex.y);
    atomicAdd(&g_den1[d * 4 + 2], ex.z);
    atomicAdd(&g_den1[d * 4 + 3], ex.w);
}

// warp per edge: gather h1[src] (128 f), scale by per-head alpha, scatter-add
__global__ void k_edgeC1(const int* __restrict__ ei) {
    int gt = blockIdx.x * blockDim.x + threadIdx.x;
    int e = gt >> 5;
    int lane = gt & 31;
    if (e >= ET) return;
    int s, d;
    if (e < EE) { s = ei[e]; d = ei[EE + e]; } else { s = e - EE; d = s; }
    float4 ev = ((const float4*)g_e1)[e];
    float4 dn = ((const float4*)g_den1)[d];
    float c0 = ev.x / (dn.x + 1e-16f);
    float c1 = ev.y / (dn.y + 1e-16f);
    float c2 = ev.z / (dn.z + 1e-16f);
    float c3 = ev.w / (dn.w + 1e-16f);
    int hd = lane >> 3;  // 4 channels per lane, 8 lanes per head
    float cf = (hd == 0) ? c0 : (hd == 1) ? c1 : (hd == 2) ? c2 : c3;
    float4 hv = ((const float4*)g_h1)[s * 32 + lane];
    float* base = &g_agg1[d * 128 + lane * 4];
    atomicAdd(base + 0, cf * hv.x);
    atomicAdd(base + 1, cf * hv.y);
    atomicAdd(base + 2, cf * hv.z);
    atomicAdd(base + 3, cf * hv.w);
}

// ---------------- layer1 activation: agg1 = elu(agg1 + b1) -----------------
__global__ void k_act1(const float* __restrict__ b1) {
    int j = blockIdx.x * blockDim.x + threadIdx.x;
    if (j >= NN * 128) return;
    float v = g_agg1[j] + b1[j & 127];
    g_agg1[j] = elu(v);
}

// ---------------- layer2 edge kernels (heads = 1) ---------------------------
__global__ void k_edgeA2(const int* __restrict__ ei) {
    int e = blockIdx.x * blockDim.x + threadIdx.x;
    if (e >= ET) return;
    int s, d;
    if (e < EE) { s = ei[e]; d = ei[EE + e]; } else { s = e - EE; d = s; }
    float l = lrelu(g_as2[s] + g_ad2[d]);
    g_e2[e] = l;
    atomicMax(&g_m2[d], fenc(l));
}

__global__ void k_edgeB2(const int* __restrict__ ei) {
    int e = blockIdx.x * blockDim.x + threadIdx.x;
    if (e >= ET) return;
    int d = (e < EE) ? ei[EE + e] : (e - EE);
    float ex = __expf(g_e2[e] - fdec(g_m2[d]));
    g_e2[e] = ex;
    atomicAdd(&g_den2[d], ex);
}

__global__ void k_edgeC2(const int* __restrict__ ei) {
    int gt = blockIdx.x * blockDim.x + threadIdx.x;
    int e = gt >> 5;
    int lane = gt & 31;
    if (e >= ET) return;
    int s, d;
    if (e < EE) { s = ei[e]; d = ei[EE + e]; } else { s = e - EE; d = s; }
    float cf = g_e2[e] / (g_den2[d] + 1e-16f);
    float4 hv = ((const float4*)g_h2)[s * 32 + lane];
    float* base = &g_agg2[d * 128 + lane * 4];
    atomicAdd(base + 0, cf * hv.x);
    atomicAdd(base + 1, cf * hv.y);
    atomicAdd(base + 2, cf * hv.z);
    atomicAdd(base + 3, cf * hv.w);
}

// ---------------- final: out = elu(agg2 + b2) -------------------------------
__global__ void k_final(const float* __restrict__ b2, float* __restrict__ out) {
    int j = blockIdx.x * blockDim.x + threadIdx.x;
    if (j >= NN * 128) return;
    float v = g_agg2[j] + b2[j & 127];
    out[j] = elu(v);
}

// ---------------- host launch ------------------------------------------------
extern "C" void kernel_launch(void* const* d_in, const int* in_sizes, int n_in,
                              void* d_out, int out_size) {
    const float* x   = (const float*)d_in[0];
    const int*   ei  = (const int*)  d_in[1];
    const float* W1  = (const float*)d_in[2];
    const float* a_s1 = (const float*)d_in[3];
    const float* a_d1 = (const float*)d_in[4];
    const float* b1  = (const float*)d_in[5];
    const float* W2  = (const float*)d_in[6];
    const float* a_s2 = (const float*)d_in[7];
    const float* a_d2 = (const float*)d_in[8];
    const float* b2  = (const float*)d_in[9];
    float* out = (float*)d_out;

    const int EB = (ET + 255) / 256;          // edge-parallel blocks
    const int WB = (ET * 32 + 255) / 256;     // warp-per-edge blocks
    const int NB = (NN * 128 + 255) / 256;    // node*channel blocks

    k_init<<<2048, 256>>>();
    k_init2<<<2048, 256>>>();

    // layer 1
    k_gemm<<<(NN + 63) / 64, 256>>>(x, W1, 0);
    k_alpha1<<<NN, 128>>>(a_s1, a_d1);
    k_edgeA1<<<EB, 256>>>(ei);
    k_edgeB1<<<EB, 256>>>(ei);
    k_edgeC1<<<WB, 256>>>(ei);
    k_act1<<<NB, 256>>>(b1);

    // layer 2
    k_gemm<<<(NN + 63) / 64, 256>>>(x /*unused*/, W2, 1);
    k_alpha2<<<NN, 128>>>(a_s2, a_d2);
    k_edgeA2<<<EB, 256>>>(ei);
    k_edgeB2<<<EB, 256>>>(ei);
    k_edgeC2<<<WB, 256>>>(ei);
    k_final<<<NB, 256>>>(b2, out);
}

// round 2
// speedup vs baseline: 3.3122x; 3.3122x over previous
#include <cuda_runtime.h>
#include <math.h>
#include <float.h>

#define NN 50000
#define EE 800000
#define ET (EE + NN)
#define SCAN_B 49   // ceil(50000/1024)

// ---------------- scratch ---------------------------------------------------
__device__ float g_h1[NN * 128];
__device__ float g_h2[NN * 128];
__device__ float g_agg1[NN * 128];
__device__ float g_as1[NN * 4];
__device__ float g_ad1[NN * 4];
__device__ float g_as2[NN];
__device__ float g_ad2[NN];
__device__ int   g_deg[NN];
__device__ int   g_scan[SCAN_B * 1024];
__device__ int   g_bsum[SCAN_B];
__device__ int   g_boff[SCAN_B];
__device__ int   g_rowptr[NN + 1];
__device__ int   g_fill[NN];
__device__ int   g_col[ET];

__device__ __forceinline__ float lrelu(float x) { return x > 0.f ? x : 0.2f * x; }
__device__ __forceinline__ float elu(float x)   { return x > 0.f ? x : expm1f(x); }

// ---------------- CSR build -------------------------------------------------
__global__ void k_zero() {
    int i = blockIdx.x * blockDim.x + threadIdx.x;
    if (i < NN) g_deg[i] = 0;
}

__global__ void k_count(const int* __restrict__ ei) {
    int e = blockIdx.x * blockDim.x + threadIdx.x;
    if (e >= ET) return;
    int d = (e < EE) ? ei[EE + e] : (e - EE);
    atomicAdd(&g_deg[d], 1);
}

__global__ void k_scan_part() {
    __shared__ int sh[1024];
    int tid = threadIdx.x;
    int i = blockIdx.x * 1024 + tid;
    int v = (i < NN) ? g_deg[i] : 0;
    sh[tid] = v;
    __syncthreads();
#pragma unroll
    for (int off = 1; off < 1024; off <<= 1) {
        int t = (tid >= off) ? sh[tid - off] : 0;
        __syncthreads();
        sh[tid] += t;
        __syncthreads();
    }
    g_scan[i] = sh[tid];
    if (tid == 1023) g_bsum[blockIdx.x] = sh[tid];
}

__global__ void k_scan_top() {
    if (threadIdx.x == 0) {
        int s = 0;
        for (int b = 0; b < SCAN_B; b++) { int t = g_bsum[b]; g_boff[b] = s; s += t; }
    }
}

__global__ void k_rowptr() {
    int i = blockIdx.x * blockDim.x + threadIdx.x;
    if (i >= NN) return;
    int incl = g_scan[i] + g_boff[i >> 10];
    g_rowptr[i + 1] = incl;
    g_fill[i] = incl - g_deg[i];
    if (i == 0) g_rowptr[0] = 0;
}

__global__ void k_fill(const int* __restrict__ ei) {
    int e = blockIdx.x * blockDim.x + threadIdx.x;
    if (e >= ET) return;
    int s, d;
    if (e < EE) { s = ei[e]; d = ei[EE + e]; } else { s = e - EE; d = s; }
    int pos = atomicAdd(&g_fill[d], 1);
    g_col[pos] = s;
}

// ---------------- GEMM [NN,128]@[128,128] + fused alpha epilogue ------------
// LAYER 0: X = x (arg), H = g_h1, alpha -> g_as1/g_ad1 (HEADS=4)
// LAYER 1: X = g_agg1,  H = g_h2, alpha -> g_as2/g_ad2 (HEADS=1)
template <int LAYER>
__global__ void k_gemm(const float* __restrict__ Xext,
                       const float* __restrict__ W,
                       const float* __restrict__ asrc,
                       const float* __restrict__ adst) {
    const float* __restrict__ X = (LAYER == 0) ? Xext : g_agg1;
    float* __restrict__ H = (LAYER == 0) ? g_h1 : g_h2;

    __shared__ float xs[64][128];
    int row0 = blockIdx.x * 64;

    for (int i = threadIdx.x; i < 64 * 32; i += 256) {
        int r = i >> 5, c4 = i & 31;
        int row = row0 + r;
        float4 v = make_float4(0.f, 0.f, 0.f, 0.f);
        if (row < NN) v = ((const float4*)X)[row * 32 + c4];
        *(float4*)(&xs[r][c4 * 4]) = v;
    }
    __syncthreads();

    int tc = threadIdx.x & 31;   // 4-col group
    int tr = threadIdx.x >> 5;   // warp id: rows tr*8 .. tr*8+7
    float acc[8][4];
#pragma unroll
    for (int r = 0; r < 8; r++)
#pragma unroll
        for (int j = 0; j < 4; j++) acc[r][j] = 0.f;

#pragma unroll 8
    for (int k = 0; k < 128; k++) {
        float4 w = ((const float4*)W)[k * 32 + tc];
#pragma unroll
        for (int r = 0; r < 8; r++) {
            float xv = xs[tr * 8 + r][k];
            acc[r][0] += xv * w.x;
            acc[r][1] += xv * w.y;
            acc[r][2] += xv * w.z;
            acc[r][3] += xv * w.w;
        }
    }

    float4 av = ((const float4*)asrc)[tc];
    float4 dv = ((const float4*)adst)[tc];

#pragma unroll
    for (int r = 0; r < 8; r++) {
        int row = row0 + tr * 8 + r;
        if (row >= NN) continue;
        ((float4*)H)[row * 32 + tc] =
            make_float4(acc[r][0], acc[r][1], acc[r][2], acc[r][3]);

        float s = acc[r][0] * av.x + acc[r][1] * av.y + acc[r][2] * av.z + acc[r][3] * av.w;
        float d = acc[r][0] * dv.x + acc[r][1] * dv.y + acc[r][2] * dv.z + acc[r][3] * dv.w;
        if (LAYER == 0) {
            // reduce within 8-lane head groups (head = tc>>3)
#pragma unroll
            for (int off = 4; off; off >>= 1) {
                s += __shfl_xor_sync(0xffffffffu, s, off);
                d += __shfl_xor_sync(0xffffffffu, d, off);
            }
            if ((tc & 7) == 0) {
                g_as1[row * 4 + (tc >> 3)] = s;
                g_ad1[row * 4 + (tc >> 3)] = d;
            }
        } else {
#pragma unroll
            for (int off = 16; off; off >>= 1) {
                s += __shfl_xor_sync(0xffffffffu, s, off);
                d += __shfl_xor_sync(0xffffffffu, d, off);
            }
            if (tc == 0) { g_as2[row] = s; g_ad2[row] = d; }
        }
    }
}

// ---------------- fused attention + aggregation, layer 1 (4 heads) ----------
// one warp per destination node; lane owns 4 channels (head = lane>>3)
__global__ void k_node1(const float* __restrict__ b1) {
    int w = (blockIdx.x * blockDim.x + threadIdx.x) >> 5;
    int lane = threadIdx.x & 31;
    if (w >= NN) return;
    int beg = g_rowptr[w], end = g_rowptr[w + 1];

    float4 ad = ((const float4*)g_ad1)[w];

    // pass 1: per-head max (lanes strided over edges)
    float4 mx = make_float4(-FLT_MAX, -FLT_MAX, -FLT_MAX, -FLT_MAX);
    for (int i = beg + lane; i < end; i += 32) {
        int s = g_col[i];
        float4 a = ((const float4*)g_as1)[s];
        mx.x = fmaxf(mx.x, lrelu(a.x + ad.x));
        mx.y = fmaxf(mx.y, lrelu(a.y + ad.y));
        mx.z = fmaxf(mx.z, lrelu(a.z + ad.z));
        mx.w = fmaxf(mx.w, lrelu(a.w + ad.w));
    }
#pragma unroll
    for (int off = 16; off; off >>= 1) {
        mx.x = fmaxf(mx.x, __shfl_xor_sync(0xffffffffu, mx.x, off));
        mx.y = fmaxf(mx.y, __shfl_xor_sync(0xffffffffu, mx.y, off));
        mx.z = fmaxf(mx.z, __shfl_xor_sync(0xffffffffu, mx.z, off));
        mx.w = fmaxf(mx.w, __shfl_xor_sync(0xffffffffu, mx.w, off));
    }

    int hd = lane >> 3;
    float mh  = (hd == 0) ? mx.x : (hd == 1) ? mx.y : (hd == 2) ? mx.z : mx.w;
    float adh = (hd == 0) ? ad.x : (hd == 1) ? ad.y : (hd == 2) ? ad.z : ad.w;

    // pass 2: unnormalized weighted aggregate + weight sum
    float ws = 0.f;
    float4 acc = make_float4(0.f, 0.f, 0.f, 0.f);
    for (int i = beg; i < end; i++) {
        int s = g_col[i];
        float a = g_as1[s * 4 + hd];
        float wt = __expf(lrelu(a + adh) - mh);
        ws += wt;
        float4 hv = ((const float4*)g_h1)[s * 32 + lane];
        acc.x += wt * hv.x;
        acc.y += wt * hv.y;
        acc.z += wt * hv.z;
        acc.w += wt * hv.w;
    }
    float inv = 1.f / (ws + 1e-16f);
    float4 bv = ((const float4*)b1)[lane];
    float4 o;
    o.x = elu(acc.x * inv + bv.x);
    o.y = elu(acc.y * inv + bv.y);
    o.z = elu(acc.z * inv + bv.z);
    o.w = elu(acc.w * inv + bv.w);
    ((float4*)g_agg1)[w * 32 + lane] = o;
}

// ---------------- fused attention + aggregation, layer 2 (1 head) -----------
__global__ void k_node2(const float* __restrict__ b2, float* __restrict__ out) {
    int w = (blockIdx.x * blockDim.x + threadIdx.x) >> 5;
    int lane = threadIdx.x & 31;
    if (w >= NN) return;
    int beg = g_rowptr[w], end = g_rowptr[w + 1];

    float adv = g_ad2[w];

    float mx = -FLT_MAX;
    for (int i = beg + lane; i < end; i += 32) {
        int s = g_col[i];
        mx = fmaxf(mx, lrelu(g_as2[s] + adv));
    }
#pragma unroll
    for (int off = 16; off; off >>= 1)
        mx = fmaxf(mx, __shfl_xor_sync(0xffffffffu, mx, off));

    float ws = 0.f;
    float4 acc = make_float4(0.f, 0.f, 0.f, 0.f);
    for (int i = beg; i < end; i++) {
        int s = g_col[i];
        float wt = __expf(lrelu(g_as2[s] + adv) - mx);
        ws += wt;
        float4 hv = ((const float4*)g_h2)[s * 32 + lane];
        acc.x += wt * hv.x;
        acc.y += wt * hv.y;
        acc.z += wt * hv.z;
        acc.w += wt * hv.w;
    }
    float inv = 1.f / (ws + 1e-16f);
    float4 bv = ((const float4*)b2)[lane];
    float4 o;
    o.x = elu(acc.x * inv + bv.x);
    o.y = elu(acc.y * inv + bv.y);
    o.z = elu(acc.z * inv + bv.z);
    o.w = elu(acc.w * inv + bv.w);
    ((float4*)out)[w * 32 + lane] = o;
}

// ---------------- host launch ------------------------------------------------
extern "C" void kernel_launch(void* const* d_in, const int* in_sizes, int n_in,
                              void* d_out, int out_size) {
    const float* x    = (const float*)d_in[0];
    const int*   ei   = (const int*)  d_in[1];
    const float* W1   = (const float*)d_in[2];
    const float* a_s1 = (const float*)d_in[3];
    const float* a_d1 = (const float*)d_in[4];
    const float* b1   = (const float*)d_in[5];
    const float* W2   = (const float*)d_in[6];
    const float* a_s2 = (const float*)d_in[7];
    const float* a_d2 = (const float*)d_in[8];
    const float* b2   = (const float*)d_in[9];
    float* out = (float*)d_out;

    const int EB = (ET + 255) / 256;
    const int NB = (NN + 255) / 256;
    const int WARPB = (NN * 32 + 255) / 256;

    // CSR build (shared by both layers)
    k_zero<<<NB, 256>>>();
    k_count<<<EB, 256>>>(ei);
    k_scan_part<<<SCAN_B, 1024>>>();
    k_scan_top<<<1, 32>>>();
    k_rowptr<<<NB, 256>>>();
    k_fill<<<EB, 256>>>(ei);

    // layer 1
    k_gemm<0><<<(NN + 63) / 64, 256>>>(x, W1, a_s1, a_d1);
    k_node1<<<WARPB, 256>>>(b1);

    // layer 2
    k_gemm<1><<<(NN + 63) / 64, 256>>>(nullptr, W2, a_s2, a_d2);
    k_node2<<<WARPB, 256>>>(b2, out);
}